// round 13
// baseline (speedup 1.0000x reference)
#include <cuda_runtime.h>
#include <cuda_fp16.h>
#include <cstdint>

// ---------------------------------------------------------------------------
// LongformerAttention  B=2, S=4096, HID=1024, H=16, D=64, W=64
// Round 13: GEMM block tile 256x128 (512 threads, 4x4 warps, warp tile 64x32
// unchanged) -> B-tile L2 traffic halves. Attention unchanged.
// ---------------------------------------------------------------------------

#define S_LEN   4096
#define HIDDEN  1024
#define NHEAD   16
#define HDIM    64
#define NCHUNK  64
#define BATCH   2
#define MROWS   (BATCH * S_LEN)   // 8192

__device__ __half g_Qh[(size_t)MROWS * HIDDEN];
__device__ __half g_Kh[(size_t)MROWS * HIDDEN];
__device__ __half g_Vh[(size_t)MROWS * HIDDEN];
__device__ __half g_ctxh[(size_t)MROWS * HIDDEN];
__device__ __half g_Xh[(size_t)MROWS * HIDDEN];
__device__ __half g_Wth[4][(size_t)HIDDEN * HIDDEN];     // fp16 TRANSPOSED W [n][k]

__device__ __forceinline__ void mma_f16(float c[4], const uint32_t a[4], const uint32_t b[2]) {
    asm volatile(
        "mma.sync.aligned.m16n8k16.row.col.f32.f16.f16.f32 "
        "{%0,%1,%2,%3}, {%4,%5,%6,%7}, {%8,%9}, {%0,%1,%2,%3};"
        : "+f"(c[0]), "+f"(c[1]), "+f"(c[2]), "+f"(c[3])
        : "r"(a[0]), "r"(a[1]), "r"(a[2]), "r"(a[3]), "r"(b[0]), "r"(b[1]));
}

__device__ __forceinline__ void cp_async16(uint32_t dst, const void* src) {
    asm volatile("cp.async.cg.shared.global [%0], [%1], 16;\n"
                 :: "r"(dst), "l"(src));
}

__device__ __forceinline__ void cp_async16z(uint32_t dst, const void* src, uint32_t n) {
    asm volatile("cp.async.cg.shared.global [%0], [%1], 16, %2;\n"
                 :: "r"(dst), "l"(src), "r"(n));
}

__device__ __forceinline__ void ldsm_x4(uint32_t r[4], uint32_t addr) {
    asm volatile("ldmatrix.sync.aligned.m8n8.x4.shared.b16 {%0,%1,%2,%3}, [%4];"
                 : "=r"(r[0]), "=r"(r[1]), "=r"(r[2]), "=r"(r[3]) : "r"(addr));
}

__device__ __forceinline__ void ldsm_x4_t(uint32_t r[4], uint32_t addr) {
    asm volatile("ldmatrix.sync.aligned.m8n8.x4.trans.shared.b16 {%0,%1,%2,%3}, [%4];"
                 : "=r"(r[0]), "=r"(r[1]), "=r"(r[2]), "=r"(r[3]) : "r"(addr));
}

// ---------------------------------------------------------------------------
// Merged prepass: z=0..3 -> transpose+convert W[z] (z=0: Wq scaled 1/8,
// bit-exact exponent shift); z=4,5 -> convert X half
// ---------------------------------------------------------------------------
__global__ __launch_bounds__(256) void prepass_kernel(
    const float* __restrict__ X,
    const float* __restrict__ w0, const float* __restrict__ w1,
    const float* __restrict__ w2, const float* __restrict__ w3,
    __half* __restrict__ Xh, __half* __restrict__ out4)
{
    const int z = blockIdx.z;
    if (z < 4) {
        __shared__ float tile[32][33];
        const float* in = (z == 0) ? w0 : (z == 1) ? w1 : (z == 2) ? w2 : w3;
        const float scale = (z == 0) ? 0.125f : 1.0f;
        __half* out = out4 + (size_t)z * HIDDEN * HIDDEN;
        int k0 = blockIdx.x * 32, n0 = blockIdx.y * 32;
        int tx = threadIdx.x & 31, ty = threadIdx.x >> 5;
#pragma unroll
        for (int i = 0; i < 32; i += 8)
            tile[ty + i][tx] = in[(size_t)(k0 + ty + i) * HIDDEN + n0 + tx];
        __syncthreads();
#pragma unroll
        for (int i = 0; i < 32; i += 8)
            out[(size_t)(n0 + ty + i) * HIDDEN + k0 + tx] =
                __float2half_rn(tile[tx][ty + i] * scale);
    } else {
        int blk = (z - 4) * 1024 + blockIdx.y * 32 + blockIdx.x;
#pragma unroll
        for (int i = 0; i < 4; i++) {
            int idx = (blk * 4 + i) * 256 + threadIdx.x;
            float4 v = ((const float4*)X)[idx];
            ((__half2*)Xh)[2 * idx]     = __floats2half2_rn(v.x, v.y);
            ((__half2*)Xh)[2 * idx + 1] = __floats2half2_rn(v.z, v.w);
        }
    }
}

// ---------------------------------------------------------------------------
// fp16 GEMM: C[M,N] = A[M,K] @ Bt[N,K]^T + bias[N]*bias_scale
// Block tile 256x128, BK=64, 512 threads (16 warps, 4x4), warp tile 64x32.
// 3-stage cp.async, fully unrolled, prefetch after first ks-step.
// ---------------------------------------------------------------------------
#define GK 1024
#define GN 1024
#define A_HALVES (256 * 72)                     // 18432
#define B_HALVES (128 * 72)                     // 9216
#define STAGE_HALVES (A_HALVES + B_HALVES)      // 27648
#define GEMM_SMEM_BYTES (3 * STAGE_HALVES * 2)  // 165888

template <bool OUT_HALF>
__device__ __forceinline__ void gemm_body_f16(
    const __half* __restrict__ A, const __half* __restrict__ Bt,
    const float* __restrict__ bias, float bias_scale,
    void* __restrict__ Cv, __half* sm)
{
    const int tid  = threadIdx.x;
    const int lane = tid & 31;
    const int wid  = tid >> 5;            // 0..15
    const int wm   = wid >> 2;            // 0..3 -> rows wm*64
    const int wn   = wid & 3;             // 0..3 -> cols wn*32
    const int qq   = lane >> 2;
    const int qk   = lane & 3;
    const int brow = blockIdx.y * 256;
    const int bcol = blockIdx.x * 128;

    const int g  = lane >> 3;
    const int lr = lane & 7;

    const uint32_t sm_u = (uint32_t)__cvta_generic_to_shared(sm);

    float acc[4][4][4];
#pragma unroll
    for (int i = 0; i < 4; i++)
#pragma unroll
        for (int j = 0; j < 4; j++)
#pragma unroll
            for (int t = 0; t < 4; t++) acc[i][j][t] = 0.f;

    const int ld_r = tid >> 3;            // 0..63
    const int ld_c = tid & 7;
    const __half* Ag = A + (size_t)(brow + ld_r) * GK + ld_c * 8;
    const __half* Bg = Bt + (size_t)(bcol + ld_r) * GK + ld_c * 8;
    const uint32_t st_off = (uint32_t)(ld_r * 144 + ld_c * 16);

    auto issue = [&](int slot, int k0) {
        uint32_t as_u = sm_u + (uint32_t)(slot * STAGE_HALVES) * 2u + st_off;
        uint32_t bs_u = as_u + (uint32_t)A_HALVES * 2u;
#pragma unroll
        for (int i = 0; i < 4; i++)       // A: 256 rows
            cp_async16(as_u + (uint32_t)(i * 64 * 144), Ag + (size_t)(i * 64) * GK + k0);
#pragma unroll
        for (int i = 0; i < 2; i++)       // B: 128 rows
            cp_async16(bs_u + (uint32_t)(i * 64 * 144), Bg + (size_t)(i * 64) * GK + k0);
        asm volatile("cp.async.commit_group;\n" ::: "memory");
    };

    issue(0, 0);
    issue(1, 64);

    const uint32_t a_off = (uint32_t)((wm * 64 + (lane & 15)) * 144 + (lane >> 4) * 16);
    const uint32_t b_off = (uint32_t)A_HALVES * 2u +
                           (uint32_t)((wn * 32 + (g >> 1) * 8 + lr) * 144 + (g & 1) * 16);

#pragma unroll
    for (int t = 0; t < 16; t++) {
        if (t == 15)
            asm volatile("cp.async.wait_group 0;\n" ::: "memory");
        else
            asm volatile("cp.async.wait_group 1;\n" ::: "memory");
        __syncthreads();

        const uint32_t base = sm_u + (uint32_t)((t % 3) * STAGE_HALVES) * 2u;
        const uint32_t a_base = base + a_off;
        const uint32_t b_base = base + b_off;

#pragma unroll
        for (int ks = 0; ks < 4; ks++) {
            const uint32_t kboff = (uint32_t)(ks * 32);
            uint32_t af[4][4];
#pragma unroll
            for (int mt = 0; mt < 4; mt++)
                ldsm_x4(af[mt], a_base + (uint32_t)(mt * 16 * 144) + kboff);
            uint32_t bf[2][4];
#pragma unroll
            for (int ntp = 0; ntp < 2; ntp++)
                ldsm_x4(bf[ntp], b_base + (uint32_t)(ntp * 16 * 144) + kboff);
#pragma unroll
            for (int mt = 0; mt < 4; mt++)
#pragma unroll
                for (int nt = 0; nt < 4; nt++)
                    mma_f16(acc[mt][nt], af[mt], &bf[nt >> 1][(nt & 1) * 2]);

            if (ks == 0 && t + 2 < 16)
                issue((t + 2) % 3, (t + 2) * 64);
        }
    }

#pragma unroll
    for (int nt = 0; nt < 4; nt++) {
        int cc = bcol + wn * 32 + nt * 8 + 2 * qk;
        float2 bv = *(const float2*)(bias + cc);
        bv.x *= bias_scale; bv.y *= bias_scale;
#pragma unroll
        for (int mt = 0; mt < 4; mt++) {
            int r = brow + wm * 64 + mt * 16 + qq;
            if (OUT_HALF) {
                __half* C = (__half*)Cv;
                *(__half2*)(C + (size_t)r * GN + cc) =
                    __floats2half2_rn(acc[mt][nt][0] + bv.x, acc[mt][nt][1] + bv.y);
                *(__half2*)(C + (size_t)(r + 8) * GN + cc) =
                    __floats2half2_rn(acc[mt][nt][2] + bv.x, acc[mt][nt][3] + bv.y);
            } else {
                float* C = (float*)Cv;
                *(float2*)(C + (size_t)r * GN + cc) =
                    make_float2(acc[mt][nt][0] + bv.x, acc[mt][nt][1] + bv.y);
                *(float2*)(C + (size_t)(r + 8) * GN + cc) =
                    make_float2(acc[mt][nt][2] + bv.x, acc[mt][nt][3] + bv.y);
            }
        }
    }
}

__global__ __launch_bounds__(512, 1) void gemm_qkv_kernel(
    const __half* __restrict__ X, const __half* __restrict__ Wt4,
    const float* __restrict__ bq, const float* __restrict__ bk,
    const float* __restrict__ bv,
    __half* __restrict__ Q, __half* __restrict__ K, __half* __restrict__ V)
{
    extern __shared__ __half smh[];
    const __half* W = Wt4 + (size_t)blockIdx.z * HIDDEN * HIDDEN;
    const float* b  = (blockIdx.z == 0) ? bq : (blockIdx.z == 1) ? bk : bv;
    const float bs  = (blockIdx.z == 0) ? 0.125f : 1.0f;
    __half*      C  = (blockIdx.z == 0) ? Q  : (blockIdx.z == 1) ? K  : V;
    gemm_body_f16<true>(X, W, b, bs, C, smh);
}

__global__ __launch_bounds__(512, 1) void gemm_o_kernel(
    const __half* __restrict__ A, const __half* __restrict__ W,
    const float* __restrict__ b, float* __restrict__ C)
{
    extern __shared__ __half smh[];
    gemm_body_f16<false>(A, W, b, 1.0f, C, smh);
}

// ---------------------------------------------------------------------------
// Banded attention (unchanged from R12)
// ---------------------------------------------------------------------------
#define QS_OFF    0
#define KS_OFF    4608
#define VS_OFF    18432
#define PH_OFF    0
#define PH_STRIDE 200
#define MISC_HALF 32256
#define ATTN_SMEM_BYTES (MISC_HALF * 2 + 704 * 4)   // 67328

__global__ __launch_bounds__(256) void attn_kernel(const float* __restrict__ maskp)
{
    extern __shared__ __half smh[];
    __half* Ph = smh + PH_OFF;
    float* vld  = (float*)(smh + MISC_HALF);
    float* redM = vld + 192;
    float* redS = redM + 256;

    const int c = blockIdx.x;
    const int h = blockIdx.y;
    const int b = blockIdx.z;
    const int tid  = threadIdx.x;
    const int lane = tid & 31;
    const int wid  = tid >> 5;
    const int wm   = wid >> 2;
    const int wn   = wid & 3;
    const int qq   = lane >> 2;
    const int qk   = lane & 3;
    const int g    = lane >> 3;
    const int lr   = lane & 7;

    const size_t headoff = (size_t)h * HDIM;
    const size_t bbase   = (size_t)b * S_LEN;
    const int base = c * 64 - 64;

    const uint32_t sm_u = (uint32_t)__cvta_generic_to_shared(smh);
    const uint32_t qs_u = sm_u + QS_OFF * 2;
    const uint32_t ks_u = sm_u + KS_OFF * 2;
    const uint32_t vs_u = sm_u + VS_OFF * 2;

#pragma unroll
    for (int it = 0; it < 2; it++) {
        int idx = tid + it * 256;
        int r = idx >> 3, cc = idx & 7;
        cp_async16(qs_u + (uint32_t)(r * 144 + cc * 16),
                   g_Qh + (bbase + c * 64 + r) * HIDDEN + headoff + cc * 8);
    }
#pragma unroll
    for (int it = 0; it < 6; it++) {
        int idx = tid + it * 256;
        int r = idx >> 3, cc = idx & 7;
        int jg = base + r;
        bool ok = (jg >= 0) && (jg < S_LEN);
        int jc = ok ? jg : 0;
        cp_async16z(ks_u + (uint32_t)(r * 144 + cc * 16),
                    g_Kh + (bbase + jc) * HIDDEN + headoff + cc * 8, ok ? 16u : 0u);
    }
    asm volatile("cp.async.commit_group;\n" ::: "memory");

#pragma unroll
    for (int it = 0; it < 6; it++) {
        int idx = tid + it * 256;
        int r = idx >> 3, cc = idx & 7;
        int jg = base + r;
        bool ok = (jg >= 0) && (jg < S_LEN);
        int jc = ok ? jg : 0;
        cp_async16z(vs_u + (uint32_t)(r * 144 + cc * 16),
                    g_Vh + (bbase + jc) * HIDDEN + headoff + cc * 8, ok ? 16u : 0u);
    }
    asm volatile("cp.async.commit_group;\n" ::: "memory");

    if (tid < 192) {
        int jg = base + tid;
        vld[tid] = (jg >= 0 && jg < S_LEN && maskp[b * S_LEN + jg] > 0.f) ? 1.f : 0.f;
    }

    asm volatile("cp.async.wait_group 1;\n" ::: "memory");
    __syncthreads();

    // ---- Phase A: S = Q K^T (pre-scaled via Wq fold)
    float acc[2][6][4];
#pragma unroll
    for (int mt = 0; mt < 2; mt++)
#pragma unroll
        for (int nt = 0; nt < 6; nt++)
#pragma unroll
            for (int t = 0; t < 4; t++) acc[mt][nt][t] = 0.f;

    {
        const uint32_t a_base = qs_u + (uint32_t)((wm * 32 + (lane & 15)) * 144 + (lane >> 4) * 16);
        const uint32_t b_base = ks_u + (uint32_t)((wn * 48 + (g >> 1) * 8 + lr) * 144 + (g & 1) * 16);
#pragma unroll
        for (int ks = 0; ks < 4; ks++) {
            const uint32_t kboff = (uint32_t)(ks * 32);
            uint32_t af[2][4];
#pragma unroll
            for (int mt = 0; mt < 2; mt++)
                ldsm_x4(af[mt], a_base + (uint32_t)(mt * 16 * 144) + kboff);
            uint32_t bf[3][4];
#pragma unroll
            for (int ntp = 0; ntp < 3; ntp++)
                ldsm_x4(bf[ntp], b_base + (uint32_t)(ntp * 16 * 144) + kboff);
#pragma unroll
            for (int mt = 0; mt < 2; mt++)
#pragma unroll
                for (int nt = 0; nt < 6; nt++)
                    mma_f16(acc[mt][nt], af[mt], &bf[nt >> 1][(nt & 1) * 2]);
        }
    }

    // ---- hoisted column validity
    bool vb[6][2];
#pragma unroll
    for (int nt = 0; nt < 6; nt++)
#pragma unroll
        for (int e = 0; e < 2; e++)
            vb[nt][e] = vld[wn * 48 + nt * 8 + 2 * qk + e] > 0.f;

    // ---- band mask + row-max partials
    float mrow[2][2];
#pragma unroll
    for (int mt = 0; mt < 2; mt++)
#pragma unroll
        for (int hf = 0; hf < 2; hf++) mrow[mt][hf] = -1e30f;

#pragma unroll
    for (int mt = 0; mt < 2; mt++)
#pragma unroll
        for (int nt = 0; nt < 6; nt++) {
            int colb = wn * 48 + nt * 8 + 2 * qk;
#pragma unroll
            for (int hf = 0; hf < 2; hf++) {
                int row = wm * 32 + mt * 16 + qq + 8 * hf;
#pragma unroll
                for (int e = 0; e < 2; e++) {
                    int col = colb + e;
                    float v = acc[mt][nt][hf * 2 + e];
                    bool ok = (col >= row) && (col <= row + 128) && vb[nt][e];
                    v = ok ? v : -1e9f;
                    acc[mt][nt][hf * 2 + e] = v;
                    mrow[mt][hf] = fmaxf(mrow[mt][hf], v);
                }
            }
        }
#pragma unroll
    for (int mt = 0; mt < 2; mt++)
#pragma unroll
        for (int hf = 0; hf < 2; hf++) {
            float m = mrow[mt][hf];
            m = fmaxf(m, __shfl_xor_sync(0xffffffffu, m, 1));
            m = fmaxf(m, __shfl_xor_sync(0xffffffffu, m, 2));
            mrow[mt][hf] = m;
        }
    if (qk == 0) {
#pragma unroll
        for (int mt = 0; mt < 2; mt++)
#pragma unroll
            for (int hf = 0; hf < 2; hf++)
                redM[wn * 64 + wm * 32 + mt * 16 + qq + 8 * hf] = mrow[mt][hf];
    }
    __syncthreads();

    // ---- global max, exp, fp16 P store (overlay), row sums
    float gmv[2][2], srow[2][2];
#pragma unroll
    for (int mt = 0; mt < 2; mt++)
#pragma unroll
        for (int hf = 0; hf < 2; hf++) {
            int row = wm * 32 + mt * 16 + qq + 8 * hf;
            float m = fmaxf(fmaxf(redM[row], redM[64 + row]),
                            fmaxf(redM[128 + row], redM[192 + row]));
            gmv[mt][hf] = m;
            srow[mt][hf] = 0.f;
        }

#pragma unroll
    for (int mt = 0; mt < 2; mt++)
#pragma unroll
        for (int nt = 0; nt < 6; nt++) {
            int colb = wn * 48 + nt * 8 + 2 * qk;
#pragma unroll
            for (int hf = 0; hf < 2; hf++) {
                int row = wm * 32 + mt * 16 + qq + 8 * hf;
                float p0 = __expf(acc[mt][nt][hf * 2 + 0] - gmv[mt][hf]);
                float p1 = __expf(acc[mt][nt][hf * 2 + 1] - gmv[mt][hf]);
                __half h0 = __float2half_rn(p0);
                __half h1 = __float2half_rn(p1);
                srow[mt][hf] += __half2float(h0) + __half2float(h1);
                *(__half2*)(Ph + row * PH_STRIDE + colb) = __halves2half2(h0, h1);
            }
        }

#pragma unroll
    for (int mt = 0; mt < 2; mt++)
#pragma unroll
        for (int hf = 0; hf < 2; hf++) {
            float s = srow[mt][hf];
            s += __shfl_xor_sync(0xffffffffu, s, 1);
            s += __shfl_xor_sync(0xffffffffu, s, 2);
            srow[mt][hf] = s;
        }
    if (qk == 0) {
#pragma unroll
        for (int mt = 0; mt < 2; mt++)
#pragma unroll
            for (int hf = 0; hf < 2; hf++)
                redS[wn * 64 + wm * 32 + mt * 16 + qq + 8 * hf] = srow[mt][hf];
    }

    asm volatile("cp.async.wait_group 0;\n" ::: "memory");
    __syncthreads();

    // ---- Phase B: ctx = P V
    float c2[2][2][4];
#pragma unroll
    for (int mt = 0; mt < 2; mt++)
#pragma unroll
        for (int nt = 0; nt < 2; nt++)
#pragma unroll
            for (int t = 0; t < 4; t++) c2[mt][nt][t] = 0.f;

    {
        const uint32_t a_base = sm_u + (uint32_t)(PH_OFF * 2 +
                                (wm * 32 + (lane & 15)) * (PH_STRIDE * 2) + (lane >> 4) * 16);
        const uint32_t bt_base = vs_u + (uint32_t)(((g & 1) * 8 + lr) * 144 +
                                 (wn * 16 + (g >> 1) * 8) * 2);
#pragma unroll
        for (int ks = 0; ks < 12; ks++) {
            uint32_t af[2][4];
#pragma unroll
            for (int mt = 0; mt < 2; mt++)
                ldsm_x4(af[mt], a_base + (uint32_t)(mt * 16 * PH_STRIDE * 2 + ks * 32));
            uint32_t bf[4];
            ldsm_x4_t(bf, bt_base + (uint32_t)(ks * 16 * 144));
#pragma unroll
            for (int mt = 0; mt < 2; mt++)
#pragma unroll
                for (int nt = 0; nt < 2; nt++)
                    mma_f16(c2[mt][nt], af[mt], &bf[nt * 2]);
        }
    }

    // ---- epilogue
#pragma unroll
    for (int mt = 0; mt < 2; mt++)
#pragma unroll
        for (int hf = 0; hf < 2; hf++) {
            int row = wm * 32 + mt * 16 + qq + 8 * hf;
            float s = redS[row] + redS[64 + row] + redS[128 + row] + redS[192 + row];
            float rinv = 1.f / s;
            __half* Og = g_ctxh + (bbase + c * 64 + row) * HIDDEN + headoff;
#pragma unroll
            for (int nt = 0; nt < 2; nt++) {
                int col = wn * 16 + nt * 8 + 2 * qk;
                *(__half2*)(Og + col) = __floats2half2_rn(c2[mt][nt][hf * 2 + 0] * rinv,
                                                          c2[mt][nt][hf * 2 + 1] * rinv);
            }
        }
}

// ---------------------------------------------------------------------------
extern "C" void kernel_launch(void* const* d_in, const int* in_sizes, int n_in,
                              void* d_out, int out_size)
{
    const float* X    = (const float*)d_in[0];
    const float* mask = (const float*)d_in[1];
    const float* Wq   = (const float*)d_in[2];
    const float* bq   = (const float*)d_in[3];
    const float* Wk   = (const float*)d_in[4];
    const float* bk   = (const float*)d_in[5];
    const float* Wv   = (const float*)d_in[6];
    const float* bv   = (const float*)d_in[7];
    const float* Wo   = (const float*)d_in[8];
    const float* bo   = (const float*)d_in[9];
    float* out = (float*)d_out;

    __half *qp, *kp, *vp, *cp, *xhp, *wtp;
    cudaGetSymbolAddress((void**)&qp, g_Qh);
    cudaGetSymbolAddress((void**)&kp, g_Kh);
    cudaGetSymbolAddress((void**)&vp, g_Vh);
    cudaGetSymbolAddress((void**)&cp, g_ctxh);
    cudaGetSymbolAddress((void**)&xhp, g_Xh);
    cudaGetSymbolAddress((void**)&wtp, g_Wth);
    __half* wt_o = wtp + 3 * (size_t)HIDDEN * HIDDEN;

    cudaFuncSetAttribute(attn_kernel, cudaFuncAttributeMaxDynamicSharedMemorySize,
                         ATTN_SMEM_BYTES);
    cudaFuncSetAttribute(gemm_qkv_kernel, cudaFuncAttributeMaxDynamicSharedMemorySize,
                         GEMM_SMEM_BYTES);
    cudaFuncSetAttribute(gemm_o_kernel, cudaFuncAttributeMaxDynamicSharedMemorySize,
                         GEMM_SMEM_BYTES);

    dim3 pgrid(32, 32, 6);
    prepass_kernel<<<pgrid, 256>>>(X, Wq, Wk, Wv, Wo, xhp, wtp);

    dim3 gqkv(HIDDEN / 128, MROWS / 256, 3);       // 8 x 32 x 3
    gemm_qkv_kernel<<<gqkv, 512, GEMM_SMEM_BYTES>>>(xhp, wtp, bq, bk, bv, qp, kp, vp);

    dim3 agrid(NCHUNK, NHEAD, BATCH);
    attn_kernel<<<agrid, 256, ATTN_SMEM_BYTES>>>(mask);

    dim3 go(HIDDEN / 128, MROWS / 256);            // 8 x 32
    gemm_o_kernel<<<go, 512, GEMM_SMEM_BYTES>>>(cp, wt_o, bo, out);
}

// round 14
// speedup vs baseline: 1.0354x; 1.0354x over previous
#include <cuda_runtime.h>
#include <cuda_fp16.h>
#include <cstdint>

// ---------------------------------------------------------------------------
// LongformerAttention  B=2, S=4096, HID=1024, H=16, D=64, W=64
// Round 14: GEMM reverted to R12 config (128x128, 256 thr, 2 blk/SM — R13's
// 256x128 regressed). Attention: band-tile skipping (25% of Phase-A MMAs and
// exp work is provably fully-masked; skip with warp-uniform guards).
// ---------------------------------------------------------------------------

#define S_LEN   4096
#define HIDDEN  1024
#define NHEAD   16
#define HDIM    64
#define NCHUNK  64
#define BATCH   2
#define MROWS   (BATCH * S_LEN)   // 8192

__device__ __half g_Qh[(size_t)MROWS * HIDDEN];
__device__ __half g_Kh[(size_t)MROWS * HIDDEN];
__device__ __half g_Vh[(size_t)MROWS * HIDDEN];
__device__ __half g_ctxh[(size_t)MROWS * HIDDEN];
__device__ __half g_Xh[(size_t)MROWS * HIDDEN];
__device__ __half g_Wth[4][(size_t)HIDDEN * HIDDEN];     // fp16 TRANSPOSED W [n][k]

__device__ __forceinline__ void mma_f16(float c[4], const uint32_t a[4], const uint32_t b[2]) {
    asm volatile(
        "mma.sync.aligned.m16n8k16.row.col.f32.f16.f16.f32 "
        "{%0,%1,%2,%3}, {%4,%5,%6,%7}, {%8,%9}, {%0,%1,%2,%3};"
        : "+f"(c[0]), "+f"(c[1]), "+f"(c[2]), "+f"(c[3])
        : "r"(a[0]), "r"(a[1]), "r"(a[2]), "r"(a[3]), "r"(b[0]), "r"(b[1]));
}

__device__ __forceinline__ void cp_async16(uint32_t dst, const void* src) {
    asm volatile("cp.async.cg.shared.global [%0], [%1], 16;\n"
                 :: "r"(dst), "l"(src));
}

__device__ __forceinline__ void cp_async16z(uint32_t dst, const void* src, uint32_t n) {
    asm volatile("cp.async.cg.shared.global [%0], [%1], 16, %2;\n"
                 :: "r"(dst), "l"(src), "r"(n));
}

__device__ __forceinline__ void ldsm_x4(uint32_t r[4], uint32_t addr) {
    asm volatile("ldmatrix.sync.aligned.m8n8.x4.shared.b16 {%0,%1,%2,%3}, [%4];"
                 : "=r"(r[0]), "=r"(r[1]), "=r"(r[2]), "=r"(r[3]) : "r"(addr));
}

__device__ __forceinline__ void ldsm_x4_t(uint32_t r[4], uint32_t addr) {
    asm volatile("ldmatrix.sync.aligned.m8n8.x4.trans.shared.b16 {%0,%1,%2,%3}, [%4];"
                 : "=r"(r[0]), "=r"(r[1]), "=r"(r[2]), "=r"(r[3]) : "r"(addr));
}

// ---------------------------------------------------------------------------
// Merged prepass (unchanged): z=0..3 -> W transpose (Wq scaled 1/8); z=4,5 -> X
// ---------------------------------------------------------------------------
__global__ __launch_bounds__(256) void prepass_kernel(
    const float* __restrict__ X,
    const float* __restrict__ w0, const float* __restrict__ w1,
    const float* __restrict__ w2, const float* __restrict__ w3,
    __half* __restrict__ Xh, __half* __restrict__ out4)
{
    const int z = blockIdx.z;
    if (z < 4) {
        __shared__ float tile[32][33];
        const float* in = (z == 0) ? w0 : (z == 1) ? w1 : (z == 2) ? w2 : w3;
        const float scale = (z == 0) ? 0.125f : 1.0f;
        __half* out = out4 + (size_t)z * HIDDEN * HIDDEN;
        int k0 = blockIdx.x * 32, n0 = blockIdx.y * 32;
        int tx = threadIdx.x & 31, ty = threadIdx.x >> 5;
#pragma unroll
        for (int i = 0; i < 32; i += 8)
            tile[ty + i][tx] = in[(size_t)(k0 + ty + i) * HIDDEN + n0 + tx];
        __syncthreads();
#pragma unroll
        for (int i = 0; i < 32; i += 8)
            out[(size_t)(n0 + ty + i) * HIDDEN + k0 + tx] =
                __float2half_rn(tile[tx][ty + i] * scale);
    } else {
        int blk = (z - 4) * 1024 + blockIdx.y * 32 + blockIdx.x;
#pragma unroll
        for (int i = 0; i < 4; i++) {
            int idx = (blk * 4 + i) * 256 + threadIdx.x;
            float4 v = ((const float4*)X)[idx];
            ((__half2*)Xh)[2 * idx]     = __floats2half2_rn(v.x, v.y);
            ((__half2*)Xh)[2 * idx + 1] = __floats2half2_rn(v.z, v.w);
        }
    }
}

// ---------------------------------------------------------------------------
// fp16 GEMM (R12 config): block 128x128, BK=64, 256 thr (8 warps 2x4),
// 3-stage cp.async, fully unrolled, prefetch after first ks-step.
// ---------------------------------------------------------------------------
#define GK 1024
#define GN 1024
#define T_HALVES (128 * 72)
#define STAGE_HALVES (2 * T_HALVES)
#define GEMM_SMEM_BYTES (3 * STAGE_HALVES * 2)  // 110592

template <bool OUT_HALF>
__device__ __forceinline__ void gemm_body_f16(
    const __half* __restrict__ A, const __half* __restrict__ Bt,
    const float* __restrict__ bias, float bias_scale,
    void* __restrict__ Cv, __half* sm)
{
    const int tid  = threadIdx.x;
    const int lane = tid & 31;
    const int wid  = tid >> 5;
    const int wm   = wid >> 2;
    const int wn   = wid & 3;
    const int qq   = lane >> 2;
    const int qk   = lane & 3;
    const int brow = blockIdx.y * 128;
    const int bcol = blockIdx.x * 128;

    const int g  = lane >> 3;
    const int lr = lane & 7;

    const uint32_t sm_u = (uint32_t)__cvta_generic_to_shared(sm);

    float acc[4][4][4];
#pragma unroll
    for (int i = 0; i < 4; i++)
#pragma unroll
        for (int j = 0; j < 4; j++)
#pragma unroll
            for (int t = 0; t < 4; t++) acc[i][j][t] = 0.f;

    const int ld_r = tid >> 3;
    const int ld_c = tid & 7;
    const __half* Ag = A + (size_t)(brow + ld_r) * GK + ld_c * 8;
    const __half* Bg = Bt + (size_t)(bcol + ld_r) * GK + ld_c * 8;
    const uint32_t st_off = (uint32_t)(ld_r * 144 + ld_c * 16);

    auto issue = [&](int slot, int k0) {
        uint32_t as_u = sm_u + (uint32_t)(slot * STAGE_HALVES) * 2u + st_off;
        uint32_t bs_u = as_u + (uint32_t)T_HALVES * 2u;
#pragma unroll
        for (int i = 0; i < 4; i++)
            cp_async16(as_u + (uint32_t)(i * 32 * 144), Ag + (size_t)(i * 32) * GK + k0);
#pragma unroll
        for (int i = 0; i < 4; i++)
            cp_async16(bs_u + (uint32_t)(i * 32 * 144), Bg + (size_t)(i * 32) * GK + k0);
        asm volatile("cp.async.commit_group;\n" ::: "memory");
    };

    issue(0, 0);
    issue(1, 64);

    const uint32_t a_off = (uint32_t)((wm * 64 + (lane & 15)) * 144 + (lane >> 4) * 16);
    const uint32_t b_off = (uint32_t)T_HALVES * 2u +
                           (uint32_t)((wn * 32 + (g >> 1) * 8 + lr) * 144 + (g & 1) * 16);

#pragma unroll
    for (int t = 0; t < 16; t++) {
        if (t == 15)
            asm volatile("cp.async.wait_group 0;\n" ::: "memory");
        else
            asm volatile("cp.async.wait_group 1;\n" ::: "memory");
        __syncthreads();

        const uint32_t base = sm_u + (uint32_t)((t % 3) * STAGE_HALVES) * 2u;
        const uint32_t a_base = base + a_off;
        const uint32_t b_base = base + b_off;

#pragma unroll
        for (int ks = 0; ks < 4; ks++) {
            const uint32_t kboff = (uint32_t)(ks * 32);
            uint32_t af[4][4];
#pragma unroll
            for (int mt = 0; mt < 4; mt++)
                ldsm_x4(af[mt], a_base + (uint32_t)(mt * 16 * 144) + kboff);
            uint32_t bf[2][4];
#pragma unroll
            for (int ntp = 0; ntp < 2; ntp++)
                ldsm_x4(bf[ntp], b_base + (uint32_t)(ntp * 16 * 144) + kboff);
#pragma unroll
            for (int mt = 0; mt < 4; mt++)
#pragma unroll
                for (int nt = 0; nt < 4; nt++)
                    mma_f16(acc[mt][nt], af[mt], &bf[nt >> 1][(nt & 1) * 2]);

            if (ks == 0 && t + 2 < 16)
                issue((t + 2) % 3, (t + 2) * 64);
        }
    }

#pragma unroll
    for (int nt = 0; nt < 4; nt++) {
        int cc = bcol + wn * 32 + nt * 8 + 2 * qk;
        float2 bv = *(const float2*)(bias + cc);
        bv.x *= bias_scale; bv.y *= bias_scale;
#pragma unroll
        for (int mt = 0; mt < 4; mt++) {
            int r = brow + wm * 64 + mt * 16 + qq;
            if (OUT_HALF) {
                __half* C = (__half*)Cv;
                *(__half2*)(C + (size_t)r * GN + cc) =
                    __floats2half2_rn(acc[mt][nt][0] + bv.x, acc[mt][nt][1] + bv.y);
                *(__half2*)(C + (size_t)(r + 8) * GN + cc) =
                    __floats2half2_rn(acc[mt][nt][2] + bv.x, acc[mt][nt][3] + bv.y);
            } else {
                float* C = (float*)Cv;
                *(float2*)(C + (size_t)r * GN + cc) =
                    make_float2(acc[mt][nt][0] + bv.x, acc[mt][nt][1] + bv.y);
                *(float2*)(C + (size_t)(r + 8) * GN + cc) =
                    make_float2(acc[mt][nt][2] + bv.x, acc[mt][nt][3] + bv.y);
            }
        }
    }
}

__global__ __launch_bounds__(256, 2) void gemm_qkv_kernel(
    const __half* __restrict__ X, const __half* __restrict__ Wt4,
    const float* __restrict__ bq, const float* __restrict__ bk,
    const float* __restrict__ bv,
    __half* __restrict__ Q, __half* __restrict__ K, __half* __restrict__ V)
{
    extern __shared__ __half smh[];
    const __half* W = Wt4 + (size_t)blockIdx.z * HIDDEN * HIDDEN;
    const float* b  = (blockIdx.z == 0) ? bq : (blockIdx.z == 1) ? bk : bv;
    const float bs  = (blockIdx.z == 0) ? 0.125f : 1.0f;
    __half*      C  = (blockIdx.z == 0) ? Q  : (blockIdx.z == 1) ? K  : V;
    gemm_body_f16<true>(X, W, b, bs, C, smh);
}

__global__ __launch_bounds__(256, 2) void gemm_o_kernel(
    const __half* __restrict__ A, const __half* __restrict__ W,
    const float* __restrict__ b, float* __restrict__ C)
{
    extern __shared__ __half smh[];
    gemm_body_f16<false>(A, W, b, 1.0f, C, smh);
}

// ---------------------------------------------------------------------------
// Banded attention with band-tile skipping. Tile (mt,nt) for warp (wm,wn)
// covers rows [wm*32+mt*16, +15], cols [wn*48+nt*8, +7]; the band
// row <= col <= row+128 makes the tile fully masked iff
// col_hi < row_lo  or  col_lo > row_hi+128. Skipped tiles: no MMA, no exp,
// store exact zeros to Ph (bit-identical: exp(-1e9-m) underflows to 0).
// ---------------------------------------------------------------------------
#define QS_OFF    0
#define KS_OFF    4608
#define VS_OFF    18432
#define PH_OFF    0
#define PH_STRIDE 200
#define MISC_HALF 32256
#define ATTN_SMEM_BYTES (MISC_HALF * 2 + 704 * 4)   // 67328

__global__ __launch_bounds__(256) void attn_kernel(const float* __restrict__ maskp)
{
    extern __shared__ __half smh[];
    __half* Ph = smh + PH_OFF;
    float* vld  = (float*)(smh + MISC_HALF);
    float* redM = vld + 192;
    float* redS = redM + 256;

    const int c = blockIdx.x;
    const int h = blockIdx.y;
    const int b = blockIdx.z;
    const int tid  = threadIdx.x;
    const int lane = tid & 31;
    const int wid  = tid >> 5;
    const int wm   = wid >> 2;
    const int wn   = wid & 3;
    const int qq   = lane >> 2;
    const int qk   = lane & 3;
    const int g    = lane >> 3;
    const int lr   = lane & 7;

    const size_t headoff = (size_t)h * HDIM;
    const size_t bbase   = (size_t)b * S_LEN;
    const int base = c * 64 - 64;

    const uint32_t sm_u = (uint32_t)__cvta_generic_to_shared(smh);
    const uint32_t qs_u = sm_u + QS_OFF * 2;
    const uint32_t ks_u = sm_u + KS_OFF * 2;
    const uint32_t vs_u = sm_u + VS_OFF * 2;

    // tile validity (warp-uniform): tv[mt][nt]
    bool tv[2][6];
#pragma unroll
    for (int mt = 0; mt < 2; mt++)
#pragma unroll
        for (int nt = 0; nt < 6; nt++) {
            int rlo = wm * 32 + mt * 16;
            int clo = wn * 48 + nt * 8;
            tv[mt][nt] = (clo + 7 >= rlo) && (clo <= rlo + 143);
        }

#pragma unroll
    for (int it = 0; it < 2; it++) {
        int idx = tid + it * 256;
        int r = idx >> 3, cc = idx & 7;
        cp_async16(qs_u + (uint32_t)(r * 144 + cc * 16),
                   g_Qh + (bbase + c * 64 + r) * HIDDEN + headoff + cc * 8);
    }
#pragma unroll
    for (int it = 0; it < 6; it++) {
        int idx = tid + it * 256;
        int r = idx >> 3, cc = idx & 7;
        int jg = base + r;
        bool ok = (jg >= 0) && (jg < S_LEN);
        int jc = ok ? jg : 0;
        cp_async16z(ks_u + (uint32_t)(r * 144 + cc * 16),
                    g_Kh + (bbase + jc) * HIDDEN + headoff + cc * 8, ok ? 16u : 0u);
    }
    asm volatile("cp.async.commit_group;\n" ::: "memory");

#pragma unroll
    for (int it = 0; it < 6; it++) {
        int idx = tid + it * 256;
        int r = idx >> 3, cc = idx & 7;
        int jg = base + r;
        bool ok = (jg >= 0) && (jg < S_LEN);
        int jc = ok ? jg : 0;
        cp_async16z(vs_u + (uint32_t)(r * 144 + cc * 16),
                    g_Vh + (bbase + jc) * HIDDEN + headoff + cc * 8, ok ? 16u : 0u);
    }
    asm volatile("cp.async.commit_group;\n" ::: "memory");

    if (tid < 192) {
        int jg = base + tid;
        vld[tid] = (jg >= 0 && jg < S_LEN && maskp[b * S_LEN + jg] > 0.f) ? 1.f : 0.f;
    }

    asm volatile("cp.async.wait_group 1;\n" ::: "memory");
    __syncthreads();

    // ---- Phase A: S = Q K^T (pre-scaled via Wq fold), masked-tile MMAs skipped
    float acc[2][6][4];
#pragma unroll
    for (int mt = 0; mt < 2; mt++)
#pragma unroll
        for (int nt = 0; nt < 6; nt++)
#pragma unroll
            for (int t = 0; t < 4; t++) acc[mt][nt][t] = 0.f;

    {
        const uint32_t a_base = qs_u + (uint32_t)((wm * 32 + (lane & 15)) * 144 + (lane >> 4) * 16);
        const uint32_t b_base = ks_u + (uint32_t)((wn * 48 + (g >> 1) * 8 + lr) * 144 + (g & 1) * 16);
#pragma unroll
        for (int ks = 0; ks < 4; ks++) {
            const uint32_t kboff = (uint32_t)(ks * 32);
            uint32_t af[2][4];
#pragma unroll
            for (int mt = 0; mt < 2; mt++)
                ldsm_x4(af[mt], a_base + (uint32_t)(mt * 16 * 144) + kboff);
            uint32_t bf[3][4];
#pragma unroll
            for (int ntp = 0; ntp < 3; ntp++)
                ldsm_x4(bf[ntp], b_base + (uint32_t)(ntp * 16 * 144) + kboff);
#pragma unroll
            for (int mt = 0; mt < 2; mt++)
#pragma unroll
                for (int nt = 0; nt < 6; nt++)
                    if (tv[mt][nt])
                        mma_f16(acc[mt][nt], af[mt], &bf[nt >> 1][(nt & 1) * 2]);
        }
    }

    // ---- hoisted column validity
    bool vb[6][2];
#pragma unroll
    for (int nt = 0; nt < 6; nt++)
#pragma unroll
        for (int e = 0; e < 2; e++)
            vb[nt][e] = vld[wn * 48 + nt * 8 + 2 * qk + e] > 0.f;

    // ---- band mask + row-max partials (valid tiles only)
    float mrow[2][2];
#pragma unroll
    for (int mt = 0; mt < 2; mt++)
#pragma unroll
        for (int hf = 0; hf < 2; hf++) mrow[mt][hf] = -1e30f;

#pragma unroll
    for (int mt = 0; mt < 2; mt++)
#pragma unroll
        for (int nt = 0; nt < 6; nt++) {
            if (!tv[mt][nt]) continue;
            int colb = wn * 48 + nt * 8 + 2 * qk;
#pragma unroll
            for (int hf = 0; hf < 2; hf++) {
                int row = wm * 32 + mt * 16 + qq + 8 * hf;
#pragma unroll
                for (int e = 0; e < 2; e++) {
                    int col = colb + e;
                    float v = acc[mt][nt][hf * 2 + e];
                    bool ok = (col >= row) && (col <= row + 128) && vb[nt][e];
                    v = ok ? v : -1e9f;
                    acc[mt][nt][hf * 2 + e] = v;
                    mrow[mt][hf] = fmaxf(mrow[mt][hf], v);
                }
            }
        }
#pragma unroll
    for (int mt = 0; mt < 2; mt++)
#pragma unroll
        for (int hf = 0; hf < 2; hf++) {
            float m = mrow[mt][hf];
            m = fmaxf(m, __shfl_xor_sync(0xffffffffu, m, 1));
            m = fmaxf(m, __shfl_xor_sync(0xffffffffu, m, 2));
            mrow[mt][hf] = m;
        }
    if (qk == 0) {
#pragma unroll
        for (int mt = 0; mt < 2; mt++)
#pragma unroll
            for (int hf = 0; hf < 2; hf++)
                redM[wn * 64 + wm * 32 + mt * 16 + qq + 8 * hf] = mrow[mt][hf];
    }
    __syncthreads();

    // ---- global max, exp (skipped tiles -> store exact zeros), row sums
    float gmv[2][2], srow[2][2];
#pragma unroll
    for (int mt = 0; mt < 2; mt++)
#pragma unroll
        for (int hf = 0; hf < 2; hf++) {
            int row = wm * 32 + mt * 16 + qq + 8 * hf;
            float m = fmaxf(fmaxf(redM[row], redM[64 + row]),
                            fmaxf(redM[128 + row], redM[192 + row]));
            gmv[mt][hf] = m;
            srow[mt][hf] = 0.f;
        }

#pragma unroll
    for (int mt = 0; mt < 2; mt++)
#pragma unroll
        for (int nt = 0; nt < 6; nt++) {
            int colb = wn * 48 + nt * 8 + 2 * qk;
#pragma unroll
            for (int hf = 0; hf < 2; hf++) {
                int row = wm * 32 + mt * 16 + qq + 8 * hf;
                if (tv[mt][nt]) {
                    float p0 = __expf(acc[mt][nt][hf * 2 + 0] - gmv[mt][hf]);
                    float p1 = __expf(acc[mt][nt][hf * 2 + 1] - gmv[mt][hf]);
                    __half h0 = __float2half_rn(p0);
                    __half h1 = __float2half_rn(p1);
                    srow[mt][hf] += __half2float(h0) + __half2float(h1);
                    *(__half2*)(Ph + row * PH_STRIDE + colb) = __halves2half2(h0, h1);
                } else {
                    *(__half2*)(Ph + row * PH_STRIDE + colb) =
                        __halves2half2(__ushort_as_half(0), __ushort_as_half(0));
                }
            }
        }

#pragma unroll
    for (int mt = 0; mt < 2; mt++)
#pragma unroll
        for (int hf = 0; hf < 2; hf++) {
            float s = srow[mt][hf];
            s += __shfl_xor_sync(0xffffffffu, s, 1);
            s += __shfl_xor_sync(0xffffffffu, s, 2);
            srow[mt][hf] = s;
        }
    if (qk == 0) {
#pragma unroll
        for (int mt = 0; mt < 2; mt++)
#pragma unroll
            for (int hf = 0; hf < 2; hf++)
                redS[wn * 64 + wm * 32 + mt * 16 + qq + 8 * hf] = srow[mt][hf];
    }

    asm volatile("cp.async.wait_group 0;\n" ::: "memory");
    __syncthreads();

    // ---- Phase B: ctx = P V
    float c2[2][2][4];
#pragma unroll
    for (int mt = 0; mt < 2; mt++)
#pragma unroll
        for (int nt = 0; nt < 2; nt++)
#pragma unroll
            for (int t = 0; t < 4; t++) c2[mt][nt][t] = 0.f;

    {
        const uint32_t a_base = sm_u + (uint32_t)(PH_OFF * 2 +
                                (wm * 32 + (lane & 15)) * (PH_STRIDE * 2) + (lane >> 4) * 16);
        const uint32_t bt_base = vs_u + (uint32_t)(((g & 1) * 8 + lr) * 144 +
                                 (wn * 16 + (g >> 1) * 8) * 2);
#pragma unroll
        for (int ks = 0; ks < 12; ks++) {
            uint32_t af[2][4];
#pragma unroll
            for (int mt = 0; mt < 2; mt++)
                ldsm_x4(af[mt], a_base + (uint32_t)(mt * 16 * PH_STRIDE * 2 + ks * 32));
            uint32_t bf[4];
            ldsm_x4_t(bf, bt_base + (uint32_t)(ks * 16 * 144));
#pragma unroll
            for (int mt = 0; mt < 2; mt++)
#pragma unroll
                for (int nt = 0; nt < 2; nt++)
                    mma_f16(c2[mt][nt], af[mt], &bf[nt * 2]);
        }
    }

    // ---- epilogue
#pragma unroll
    for (int mt = 0; mt < 2; mt++)
#pragma unroll
        for (int hf = 0; hf < 2; hf++) {
            int row = wm * 32 + mt * 16 + qq + 8 * hf;
            float s = redS[row] + redS[64 + row] + redS[128 + row] + redS[192 + row];
            float rinv = 1.f / s;
            __half* Og = g_ctxh + (bbase + c * 64 + row) * HIDDEN + headoff;
#pragma unroll
            for (int nt = 0; nt < 2; nt++) {
                int col = wn * 16 + nt * 8 + 2 * qk;
                *(__half2*)(Og + col) = __floats2half2_rn(c2[mt][nt][hf * 2 + 0] * rinv,
                                                          c2[mt][nt][hf * 2 + 1] * rinv);
            }
        }
}

// ---------------------------------------------------------------------------
extern "C" void kernel_launch(void* const* d_in, const int* in_sizes, int n_in,
                              void* d_out, int out_size)
{
    const float* X    = (const float*)d_in[0];
    const float* mask = (const float*)d_in[1];
    const float* Wq   = (const float*)d_in[2];
    const float* bq   = (const float*)d_in[3];
    const float* Wk   = (const float*)d_in[4];
    const float* bk   = (const float*)d_in[5];
    const float* Wv   = (const float*)d_in[6];
    const float* bv   = (const float*)d_in[7];
    const float* Wo   = (const float*)d_in[8];
    const float* bo   = (const float*)d_in[9];
    float* out = (float*)d_out;

    __half *qp, *kp, *vp, *cp, *xhp, *wtp;
    cudaGetSymbolAddress((void**)&qp, g_Qh);
    cudaGetSymbolAddress((void**)&kp, g_Kh);
    cudaGetSymbolAddress((void**)&vp, g_Vh);
    cudaGetSymbolAddress((void**)&cp, g_ctxh);
    cudaGetSymbolAddress((void**)&xhp, g_Xh);
    cudaGetSymbolAddress((void**)&wtp, g_Wth);
    __half* wt_o = wtp + 3 * (size_t)HIDDEN * HIDDEN;

    cudaFuncSetAttribute(attn_kernel, cudaFuncAttributeMaxDynamicSharedMemorySize,
                         ATTN_SMEM_BYTES);
    cudaFuncSetAttribute(gemm_qkv_kernel, cudaFuncAttributeMaxDynamicSharedMemorySize,
                         GEMM_SMEM_BYTES);
    cudaFuncSetAttribute(gemm_o_kernel, cudaFuncAttributeMaxDynamicSharedMemorySize,
                         GEMM_SMEM_BYTES);

    dim3 pgrid(32, 32, 6);
    prepass_kernel<<<pgrid, 256>>>(X, Wq, Wk, Wv, Wo, xhp, wtp);

    dim3 gqkv(HIDDEN / 128, MROWS / 128, 3);       // 8 x 64 x 3
    gemm_qkv_kernel<<<gqkv, 256, GEMM_SMEM_BYTES>>>(xhp, wtp, bq, bk, bv, qp, kp, vp);

    dim3 agrid(NCHUNK, NHEAD, BATCH);
    attn_kernel<<<agrid, 256, ATTN_SMEM_BYTES>>>(mask);

    dim3 go(HIDDEN / 128, MROWS / 128);            // 8 x 64
    gemm_o_kernel<<<go, 256, GEMM_SMEM_BYTES>>>(cp, wt_o, bo, out);
}

// round 15
// speedup vs baseline: 1.1001x; 1.0625x over previous
#include <cuda_runtime.h>
#include <cuda_fp16.h>
#include <cstdint>

// ---------------------------------------------------------------------------
// LongformerAttention  B=2, S=4096, HID=1024, H=16, D=64, W=64
// Round 15: attention reverted to R12 exact. GEMM: launch_bounds(256) (255-reg
// budget, 1 blk/SM) + manual fragment double-buffering across ks-steps to
// close the 46% tensor-pipe idle from LDSM scoreboard stalls.
// ---------------------------------------------------------------------------

#define S_LEN   4096
#define HIDDEN  1024
#define NHEAD   16
#define HDIM    64
#define NCHUNK  64
#define BATCH   2
#define MROWS   (BATCH * S_LEN)   // 8192

__device__ __half g_Qh[(size_t)MROWS * HIDDEN];
__device__ __half g_Kh[(size_t)MROWS * HIDDEN];
__device__ __half g_Vh[(size_t)MROWS * HIDDEN];
__device__ __half g_ctxh[(size_t)MROWS * HIDDEN];
__device__ __half g_Xh[(size_t)MROWS * HIDDEN];
__device__ __half g_Wth[4][(size_t)HIDDEN * HIDDEN];     // fp16 TRANSPOSED W [n][k]

__device__ __forceinline__ void mma_f16(float c[4], const uint32_t a[4], const uint32_t b[2]) {
    asm volatile(
        "mma.sync.aligned.m16n8k16.row.col.f32.f16.f16.f32 "
        "{%0,%1,%2,%3}, {%4,%5,%6,%7}, {%8,%9}, {%0,%1,%2,%3};"
        : "+f"(c[0]), "+f"(c[1]), "+f"(c[2]), "+f"(c[3])
        : "r"(a[0]), "r"(a[1]), "r"(a[2]), "r"(a[3]), "r"(b[0]), "r"(b[1]));
}

__device__ __forceinline__ void cp_async16(uint32_t dst, const void* src) {
    asm volatile("cp.async.cg.shared.global [%0], [%1], 16;\n"
                 :: "r"(dst), "l"(src));
}

__device__ __forceinline__ void cp_async16z(uint32_t dst, const void* src, uint32_t n) {
    asm volatile("cp.async.cg.shared.global [%0], [%1], 16, %2;\n"
                 :: "r"(dst), "l"(src), "r"(n));
}

__device__ __forceinline__ void ldsm_x4(uint32_t r[4], uint32_t addr) {
    asm volatile("ldmatrix.sync.aligned.m8n8.x4.shared.b16 {%0,%1,%2,%3}, [%4];"
                 : "=r"(r[0]), "=r"(r[1]), "=r"(r[2]), "=r"(r[3]) : "r"(addr));
}

__device__ __forceinline__ void ldsm_x4_t(uint32_t r[4], uint32_t addr) {
    asm volatile("ldmatrix.sync.aligned.m8n8.x4.trans.shared.b16 {%0,%1,%2,%3}, [%4];"
                 : "=r"(r[0]), "=r"(r[1]), "=r"(r[2]), "=r"(r[3]) : "r"(addr));
}

// ---------------------------------------------------------------------------
// Merged prepass (unchanged)
// ---------------------------------------------------------------------------
__global__ __launch_bounds__(256) void prepass_kernel(
    const float* __restrict__ X,
    const float* __restrict__ w0, const float* __restrict__ w1,
    const float* __restrict__ w2, const float* __restrict__ w3,
    __half* __restrict__ Xh, __half* __restrict__ out4)
{
    const int z = blockIdx.z;
    if (z < 4) {
        __shared__ float tile[32][33];
        const float* in = (z == 0) ? w0 : (z == 1) ? w1 : (z == 2) ? w2 : w3;
        const float scale = (z == 0) ? 0.125f : 1.0f;
        __half* out = out4 + (size_t)z * HIDDEN * HIDDEN;
        int k0 = blockIdx.x * 32, n0 = blockIdx.y * 32;
        int tx = threadIdx.x & 31, ty = threadIdx.x >> 5;
#pragma unroll
        for (int i = 0; i < 32; i += 8)
            tile[ty + i][tx] = in[(size_t)(k0 + ty + i) * HIDDEN + n0 + tx];
        __syncthreads();
#pragma unroll
        for (int i = 0; i < 32; i += 8)
            out[(size_t)(n0 + ty + i) * HIDDEN + k0 + tx] =
                __float2half_rn(tile[tx][ty + i] * scale);
    } else {
        int blk = (z - 4) * 1024 + blockIdx.y * 32 + blockIdx.x;
#pragma unroll
        for (int i = 0; i < 4; i++) {
            int idx = (blk * 4 + i) * 256 + threadIdx.x;
            float4 v = ((const float4*)X)[idx];
            ((__half2*)Xh)[2 * idx]     = __floats2half2_rn(v.x, v.y);
            ((__half2*)Xh)[2 * idx + 1] = __floats2half2_rn(v.z, v.w);
        }
    }
}

// ---------------------------------------------------------------------------
// fp16 GEMM: block 128x128, BK=64, 256 thr (8 warps 2x4), 3-stage cp.async,
// fully unrolled, MANUAL fragment double-buffer across ks (255-reg budget).
// ---------------------------------------------------------------------------
#define GK 1024
#define GN 1024
#define T_HALVES (128 * 72)
#define STAGE_HALVES (2 * T_HALVES)
#define GEMM_SMEM_BYTES (3 * STAGE_HALVES * 2)  // 110592

template <bool OUT_HALF>
__device__ __forceinline__ void gemm_body_f16(
    const __half* __restrict__ A, const __half* __restrict__ Bt,
    const float* __restrict__ bias, float bias_scale,
    void* __restrict__ Cv, __half* sm)
{
    const int tid  = threadIdx.x;
    const int lane = tid & 31;
    const int wid  = tid >> 5;
    const int wm   = wid >> 2;
    const int wn   = wid & 3;
    const int qq   = lane >> 2;
    const int qk   = lane & 3;
    const int brow = blockIdx.y * 128;
    const int bcol = blockIdx.x * 128;

    const int g  = lane >> 3;
    const int lr = lane & 7;

    const uint32_t sm_u = (uint32_t)__cvta_generic_to_shared(sm);

    float acc[4][4][4];
#pragma unroll
    for (int i = 0; i < 4; i++)
#pragma unroll
        for (int j = 0; j < 4; j++)
#pragma unroll
            for (int t = 0; t < 4; t++) acc[i][j][t] = 0.f;

    const int ld_r = tid >> 3;
    const int ld_c = tid & 7;
    const __half* Ag = A + (size_t)(brow + ld_r) * GK + ld_c * 8;
    const __half* Bg = Bt + (size_t)(bcol + ld_r) * GK + ld_c * 8;
    const uint32_t st_off = (uint32_t)(ld_r * 144 + ld_c * 16);

    auto issue = [&](int slot, int k0) {
        uint32_t as_u = sm_u + (uint32_t)(slot * STAGE_HALVES) * 2u + st_off;
        uint32_t bs_u = as_u + (uint32_t)T_HALVES * 2u;
#pragma unroll
        for (int i = 0; i < 4; i++)
            cp_async16(as_u + (uint32_t)(i * 32 * 144), Ag + (size_t)(i * 32) * GK + k0);
#pragma unroll
        for (int i = 0; i < 4; i++)
            cp_async16(bs_u + (uint32_t)(i * 32 * 144), Bg + (size_t)(i * 32) * GK + k0);
        asm volatile("cp.async.commit_group;\n" ::: "memory");
    };

    issue(0, 0);
    issue(1, 64);

    const uint32_t a_off = (uint32_t)((wm * 64 + (lane & 15)) * 144 + (lane >> 4) * 16);
    const uint32_t b_off = (uint32_t)T_HALVES * 2u +
                           (uint32_t)((wn * 32 + (g >> 1) * 8 + lr) * 144 + (g & 1) * 16);

#pragma unroll
    for (int t = 0; t < 16; t++) {
        if (t == 15)
            asm volatile("cp.async.wait_group 0;\n" ::: "memory");
        else
            asm volatile("cp.async.wait_group 1;\n" ::: "memory");
        __syncthreads();

        const uint32_t base = sm_u + (uint32_t)((t % 3) * STAGE_HALVES) * 2u;
        const uint32_t a_base = base + a_off;
        const uint32_t b_base = base + b_off;

        // fragment double buffers across ks-steps
        uint32_t af[2][4][4];
        uint32_t bf[2][2][4];

        // prime ks=0
#pragma unroll
        for (int mt = 0; mt < 4; mt++)
            ldsm_x4(af[0][mt], a_base + (uint32_t)(mt * 16 * 144));
#pragma unroll
        for (int ntp = 0; ntp < 2; ntp++)
            ldsm_x4(bf[0][ntp], b_base + (uint32_t)(ntp * 16 * 144));

#pragma unroll
        for (int ks = 0; ks < 4; ks++) {
            const int cur = ks & 1;
            // prefetch ks+1 fragments before consuming ks (hides LDSM latency)
            if (ks < 3) {
                const uint32_t kboff = (uint32_t)((ks + 1) * 32);
#pragma unroll
                for (int mt = 0; mt < 4; mt++)
                    ldsm_x4(af[cur ^ 1][mt], a_base + (uint32_t)(mt * 16 * 144) + kboff);
#pragma unroll
                for (int ntp = 0; ntp < 2; ntp++)
                    ldsm_x4(bf[cur ^ 1][ntp], b_base + (uint32_t)(ntp * 16 * 144) + kboff);
            }
#pragma unroll
            for (int mt = 0; mt < 4; mt++)
#pragma unroll
                for (int nt = 0; nt < 4; nt++)
                    mma_f16(acc[mt][nt], af[cur][mt], &bf[cur][nt >> 1][(nt & 1) * 2]);

            if (ks == 0 && t + 2 < 16)
                issue((t + 2) % 3, (t + 2) * 64);
        }
    }

#pragma unroll
    for (int nt = 0; nt < 4; nt++) {
        int cc = bcol + wn * 32 + nt * 8 + 2 * qk;
        float2 bv = *(const float2*)(bias + cc);
        bv.x *= bias_scale; bv.y *= bias_scale;
#pragma unroll
        for (int mt = 0; mt < 4; mt++) {
            int r = brow + wm * 64 + mt * 16 + qq;
            if (OUT_HALF) {
                __half* C = (__half*)Cv;
                *(__half2*)(C + (size_t)r * GN + cc) =
                    __floats2half2_rn(acc[mt][nt][0] + bv.x, acc[mt][nt][1] + bv.y);
                *(__half2*)(C + (size_t)(r + 8) * GN + cc) =
                    __floats2half2_rn(acc[mt][nt][2] + bv.x, acc[mt][nt][3] + bv.y);
            } else {
                float* C = (float*)Cv;
                *(float2*)(C + (size_t)r * GN + cc) =
                    make_float2(acc[mt][nt][0] + bv.x, acc[mt][nt][1] + bv.y);
                *(float2*)(C + (size_t)(r + 8) * GN + cc) =
                    make_float2(acc[mt][nt][2] + bv.x, acc[mt][nt][3] + bv.y);
            }
        }
    }
}

__global__ __launch_bounds__(256) void gemm_qkv_kernel(
    const __half* __restrict__ X, const __half* __restrict__ Wt4,
    const float* __restrict__ bq, const float* __restrict__ bk,
    const float* __restrict__ bv,
    __half* __restrict__ Q, __half* __restrict__ K, __half* __restrict__ V)
{
    extern __shared__ __half smh[];
    const __half* W = Wt4 + (size_t)blockIdx.z * HIDDEN * HIDDEN;
    const float* b  = (blockIdx.z == 0) ? bq : (blockIdx.z == 1) ? bk : bv;
    const float bs  = (blockIdx.z == 0) ? 0.125f : 1.0f;
    __half*      C  = (blockIdx.z == 0) ? Q  : (blockIdx.z == 1) ? K  : V;
    gemm_body_f16<true>(X, W, b, bs, C, smh);
}

__global__ __launch_bounds__(256) void gemm_o_kernel(
    const __half* __restrict__ A, const __half* __restrict__ W,
    const float* __restrict__ b, float* __restrict__ C)
{
    extern __shared__ __half smh[];
    gemm_body_f16<false>(A, W, b, 1.0f, C, smh);
}

// ---------------------------------------------------------------------------
// Banded attention: R12 EXACT (no tile skipping — R14 falsified it)
// ---------------------------------------------------------------------------
#define QS_OFF    0
#define KS_OFF    4608
#define VS_OFF    18432
#define PH_OFF    0
#define PH_STRIDE 200
#define MISC_HALF 32256
#define ATTN_SMEM_BYTES (MISC_HALF * 2 + 704 * 4)   // 67328

__global__ __launch_bounds__(256) void attn_kernel(const float* __restrict__ maskp)
{
    extern __shared__ __half smh[];
    __half* Ph = smh + PH_OFF;
    float* vld  = (float*)(smh + MISC_HALF);
    float* redM = vld + 192;
    float* redS = redM + 256;

    const int c = blockIdx.x;
    const int h = blockIdx.y;
    const int b = blockIdx.z;
    const int tid  = threadIdx.x;
    const int lane = tid & 31;
    const int wid  = tid >> 5;
    const int wm   = wid >> 2;
    const int wn   = wid & 3;
    const int qq   = lane >> 2;
    const int qk   = lane & 3;
    const int g    = lane >> 3;
    const int lr   = lane & 7;

    const size_t headoff = (size_t)h * HDIM;
    const size_t bbase   = (size_t)b * S_LEN;
    const int base = c * 64 - 64;

    const uint32_t sm_u = (uint32_t)__cvta_generic_to_shared(smh);
    const uint32_t qs_u = sm_u + QS_OFF * 2;
    const uint32_t ks_u = sm_u + KS_OFF * 2;
    const uint32_t vs_u = sm_u + VS_OFF * 2;

#pragma unroll
    for (int it = 0; it < 2; it++) {
        int idx = tid + it * 256;
        int r = idx >> 3, cc = idx & 7;
        cp_async16(qs_u + (uint32_t)(r * 144 + cc * 16),
                   g_Qh + (bbase + c * 64 + r) * HIDDEN + headoff + cc * 8);
    }
#pragma unroll
    for (int it = 0; it < 6; it++) {
        int idx = tid + it * 256;
        int r = idx >> 3, cc = idx & 7;
        int jg = base + r;
        bool ok = (jg >= 0) && (jg < S_LEN);
        int jc = ok ? jg : 0;
        cp_async16z(ks_u + (uint32_t)(r * 144 + cc * 16),
                    g_Kh + (bbase + jc) * HIDDEN + headoff + cc * 8, ok ? 16u : 0u);
    }
    asm volatile("cp.async.commit_group;\n" ::: "memory");

#pragma unroll
    for (int it = 0; it < 6; it++) {
        int idx = tid + it * 256;
        int r = idx >> 3, cc = idx & 7;
        int jg = base + r;
        bool ok = (jg >= 0) && (jg < S_LEN);
        int jc = ok ? jg : 0;
        cp_async16z(vs_u + (uint32_t)(r * 144 + cc * 16),
                    g_Vh + (bbase + jc) * HIDDEN + headoff + cc * 8, ok ? 16u : 0u);
    }
    asm volatile("cp.async.commit_group;\n" ::: "memory");

    if (tid < 192) {
        int jg = base + tid;
        vld[tid] = (jg >= 0 && jg < S_LEN && maskp[b * S_LEN + jg] > 0.f) ? 1.f : 0.f;
    }

    asm volatile("cp.async.wait_group 1;\n" ::: "memory");
    __syncthreads();

    // ---- Phase A: S = Q K^T (pre-scaled via Wq fold)
    float acc[2][6][4];
#pragma unroll
    for (int mt = 0; mt < 2; mt++)
#pragma unroll
        for (int nt = 0; nt < 6; nt++)
#pragma unroll
            for (int t = 0; t < 4; t++) acc[mt][nt][t] = 0.f;

    {
        const uint32_t a_base = qs_u + (uint32_t)((wm * 32 + (lane & 15)) * 144 + (lane >> 4) * 16);
        const uint32_t b_base = ks_u + (uint32_t)((wn * 48 + (g >> 1) * 8 + lr) * 144 + (g & 1) * 16);
#pragma unroll
        for (int ks = 0; ks < 4; ks++) {
            const uint32_t kboff = (uint32_t)(ks * 32);
            uint32_t af[2][4];
#pragma unroll
            for (int mt = 0; mt < 2; mt++)
                ldsm_x4(af[mt], a_base + (uint32_t)(mt * 16 * 144) + kboff);
            uint32_t bf[3][4];
#pragma unroll
            for (int ntp = 0; ntp < 3; ntp++)
                ldsm_x4(bf[ntp], b_base + (uint32_t)(ntp * 16 * 144) + kboff);
#pragma unroll
            for (int mt = 0; mt < 2; mt++)
#pragma unroll
                for (int nt = 0; nt < 6; nt++)
                    mma_f16(acc[mt][nt], af[mt], &bf[nt >> 1][(nt & 1) * 2]);
        }
    }

    // ---- hoisted column validity
    bool vb[6][2];
#pragma unroll
    for (int nt = 0; nt < 6; nt++)
#pragma unroll
        for (int e = 0; e < 2; e++)
            vb[nt][e] = vld[wn * 48 + nt * 8 + 2 * qk + e] > 0.f;

    // ---- band mask + row-max partials
    float mrow[2][2];
#pragma unroll
    for (int mt = 0; mt < 2; mt++)
#pragma unroll
        for (int hf = 0; hf < 2; hf++) mrow[mt][hf] = -1e30f;

#pragma unroll
    for (int mt = 0; mt < 2; mt++)
#pragma unroll
        for (int nt = 0; nt < 6; nt++) {
            int colb = wn * 48 + nt * 8 + 2 * qk;
#pragma unroll
            for (int hf = 0; hf < 2; hf++) {
                int row = wm * 32 + mt * 16 + qq + 8 * hf;
#pragma unroll
                for (int e = 0; e < 2; e++) {
                    int col = colb + e;
                    float v = acc[mt][nt][hf * 2 + e];
                    bool ok = (col >= row) && (col <= row + 128) && vb[nt][e];
                    v = ok ? v : -1e9f;
                    acc[mt][nt][hf * 2 + e] = v;
                    mrow[mt][hf] = fmaxf(mrow[mt][hf], v);
                }
            }
        }
#pragma unroll
    for (int mt = 0; mt < 2; mt++)
#pragma unroll
        for (int hf = 0; hf < 2; hf++) {
            float m = mrow[mt][hf];
            m = fmaxf(m, __shfl_xor_sync(0xffffffffu, m, 1));
            m = fmaxf(m, __shfl_xor_sync(0xffffffffu, m, 2));
            mrow[mt][hf] = m;
        }
    if (qk == 0) {
#pragma unroll
        for (int mt = 0; mt < 2; mt++)
#pragma unroll
            for (int hf = 0; hf < 2; hf++)
                redM[wn * 64 + wm * 32 + mt * 16 + qq + 8 * hf] = mrow[mt][hf];
    }
    __syncthreads();

    // ---- global max, exp, fp16 P store (overlay), row sums
    float gmv[2][2], srow[2][2];
#pragma unroll
    for (int mt = 0; mt < 2; mt++)
#pragma unroll
        for (int hf = 0; hf < 2; hf++) {
            int row = wm * 32 + mt * 16 + qq + 8 * hf;
            float m = fmaxf(fmaxf(redM[row], redM[64 + row]),
                            fmaxf(redM[128 + row], redM[192 + row]));
            gmv[mt][hf] = m;
            srow[mt][hf] = 0.f;
        }

#pragma unroll
    for (int mt = 0; mt < 2; mt++)
#pragma unroll
        for (int nt = 0; nt < 6; nt++) {
            int colb = wn * 48 + nt * 8 + 2 * qk;
#pragma unroll
            for (int hf = 0; hf < 2; hf++) {
                int row = wm * 32 + mt * 16 + qq + 8 * hf;
                float p0 = __expf(acc[mt][nt][hf * 2 + 0] - gmv[mt][hf]);
                float p1 = __expf(acc[mt][nt][hf * 2 + 1] - gmv[mt][hf]);
                __half h0 = __float2half_rn(p0);
                __half h1 = __float2half_rn(p1);
                srow[mt][hf] += __half2float(h0) + __half2float(h1);
                *(__half2*)(Ph + row * PH_STRIDE + colb) = __halves2half2(h0, h1);
            }
        }

#pragma unroll
    for (int mt = 0; mt < 2; mt++)
#pragma unroll
        for (int hf = 0; hf < 2; hf++) {
            float s = srow[mt][hf];
            s += __shfl_xor_sync(0xffffffffu, s, 1);
            s += __shfl_xor_sync(0xffffffffu, s, 2);
            srow[mt][hf] = s;
        }
    if (qk == 0) {
#pragma unroll
        for (int mt = 0; mt < 2; mt++)
#pragma unroll
            for (int hf = 0; hf < 2; hf++)
                redS[wn * 64 + wm * 32 + mt * 16 + qq + 8 * hf] = srow[mt][hf];
    }

    asm volatile("cp.async.wait_group 0;\n" ::: "memory");
    __syncthreads();

    // ---- Phase B: ctx = P V
    float c2[2][2][4];
#pragma unroll
    for (int mt = 0; mt < 2; mt++)
#pragma unroll
        for (int nt = 0; nt < 2; nt++)
#pragma unroll
            for (int t = 0; t < 4; t++) c2[mt][nt][t] = 0.f;

    {
        const uint32_t a_base = sm_u + (uint32_t)(PH_OFF * 2 +
                                (wm * 32 + (lane & 15)) * (PH_STRIDE * 2) + (lane >> 4) * 16);
        const uint32_t bt_base = vs_u + (uint32_t)(((g & 1) * 8 + lr) * 144 +
                                 (wn * 16 + (g >> 1) * 8) * 2);
#pragma unroll
        for (int ks = 0; ks < 12; ks++) {
            uint32_t af[2][4];
#pragma unroll
            for (int mt = 0; mt < 2; mt++)
                ldsm_x4(af[mt], a_base + (uint32_t)(mt * 16 * PH_STRIDE * 2 + ks * 32));
            uint32_t bf[4];
            ldsm_x4_t(bf, bt_base + (uint32_t)(ks * 16 * 144));
#pragma unroll
            for (int mt = 0; mt < 2; mt++)
#pragma unroll
                for (int nt = 0; nt < 2; nt++)
                    mma_f16(c2[mt][nt], af[mt], &bf[nt * 2]);
        }
    }

    // ---- epilogue
#pragma unroll
    for (int mt = 0; mt < 2; mt++)
#pragma unroll
        for (int hf = 0; hf < 2; hf++) {
            int row = wm * 32 + mt * 16 + qq + 8 * hf;
            float s = redS[row] + redS[64 + row] + redS[128 + row] + redS[192 + row];
            float rinv = 1.f / s;
            __half* Og = g_ctxh + (bbase + c * 64 + row) * HIDDEN + headoff;
#pragma unroll
            for (int nt = 0; nt < 2; nt++) {
                int col = wn * 16 + nt * 8 + 2 * qk;
                *(__half2*)(Og + col) = __floats2half2_rn(c2[mt][nt][hf * 2 + 0] * rinv,
                                                          c2[mt][nt][hf * 2 + 1] * rinv);
            }
        }
}

// ---------------------------------------------------------------------------
extern "C" void kernel_launch(void* const* d_in, const int* in_sizes, int n_in,
                              void* d_out, int out_size)
{
    const float* X    = (const float*)d_in[0];
    const float* mask = (const float*)d_in[1];
    const float* Wq   = (const float*)d_in[2];
    const float* bq   = (const float*)d_in[3];
    const float* Wk   = (const float*)d_in[4];
    const float* bk   = (const float*)d_in[5];
    const float* Wv   = (const float*)d_in[6];
    const float* bv   = (const float*)d_in[7];
    const float* Wo   = (const float*)d_in[8];
    const float* bo   = (const float*)d_in[9];
    float* out = (float*)d_out;

    __half *qp, *kp, *vp, *cp, *xhp, *wtp;
    cudaGetSymbolAddress((void**)&qp, g_Qh);
    cudaGetSymbolAddress((void**)&kp, g_Kh);
    cudaGetSymbolAddress((void**)&vp, g_Vh);
    cudaGetSymbolAddress((void**)&cp, g_ctxh);
    cudaGetSymbolAddress((void**)&xhp, g_Xh);
    cudaGetSymbolAddress((void**)&wtp, g_Wth);
    __half* wt_o = wtp + 3 * (size_t)HIDDEN * HIDDEN;

    cudaFuncSetAttribute(attn_kernel, cudaFuncAttributeMaxDynamicSharedMemorySize,
                         ATTN_SMEM_BYTES);
    cudaFuncSetAttribute(gemm_qkv_kernel, cudaFuncAttributeMaxDynamicSharedMemorySize,
                         GEMM_SMEM_BYTES);
    cudaFuncSetAttribute(gemm_o_kernel, cudaFuncAttributeMaxDynamicSharedMemorySize,
                         GEMM_SMEM_BYTES);

    dim3 pgrid(32, 32, 6);
    prepass_kernel<<<pgrid, 256>>>(X, Wq, Wk, Wv, Wo, xhp, wtp);

    dim3 gqkv(HIDDEN / 128, MROWS / 128, 3);       // 8 x 64 x 3
    gemm_qkv_kernel<<<gqkv, 256, GEMM_SMEM_BYTES>>>(xhp, wtp, bq, bk, bv, qp, kp, vp);

    dim3 agrid(NCHUNK, NHEAD, BATCH);
    attn_kernel<<<agrid, 256, ATTN_SMEM_BYTES>>>(mask);

    dim3 go(HIDDEN / 128, MROWS / 128);            // 8 x 64
    gemm_o_kernel<<<go, 256, GEMM_SMEM_BYTES>>>(cp, wt_o, bo, out);
}